// round 2
// baseline (speedup 1.0000x reference)
#include <cuda_runtime.h>
#include <cstdint>
#include <cstddef>

#define NN 10000
#define DD 128

// ---------------- scratch (device globals; no allocations allowed) ----------
__device__ float g_xn[(size_t)NN * DD];            // normalized feats
__device__ float g_sim[(size_t)NN * NN];           // 400MB similarity matrix
__device__ int   g_knn[(size_t)NN * 16];           // top-16 per row (sorted desc)
__device__ float g_coef[(size_t)5 * NN * 32];      // per-branch coef[j]

// ---------------- 1) normalize ----------------------------------------------
__global__ void norm_kernel(const float* __restrict__ feats) {
    int n = blockIdx.x;
    int tid = threadIdx.x;                          // 128 threads = d
    float v = feats[(size_t)n * DD + tid];
    float s = v * v;
    #pragma unroll
    for (int m = 16; m >= 1; m >>= 1) s += __shfl_xor_sync(0xffffffffu, s, m);
    __shared__ float ws[4];
    if ((tid & 31) == 0) ws[tid >> 5] = s;
    __syncthreads();
    float tot = ws[0] + ws[1] + ws[2] + ws[3];
    float nrm = fmaxf(sqrtf(tot), 1e-12f);
    g_xn[(size_t)n * DD + tid] = v / nrm;
}

// ---------------- 2) sim = xn @ xn^T  (64x64 tile, 4x4 register tile) -------
__global__ void sim_gemm() {
    extern __shared__ float sm[];
    float* As = sm;                 // [128][64]  layout [d][row]
    float* Bs = sm + 128 * 64;      // [128][64]
    int tid = threadIdx.x;
    int q0 = blockIdx.y * 64;
    int k0 = blockIdx.x * 64;

    // load tiles transposed: e -> (d4, row). lanes vary row -> conflict-free STS
    for (int e = tid; e < 2048; e += 256) {
        int d4 = e >> 6;            // 0..31
        int r  = e & 63;            // 0..63
        float4 va = make_float4(0.f, 0.f, 0.f, 0.f);
        float4 vb = va;
        if (q0 + r < NN) va = *(const float4*)&g_xn[(size_t)(q0 + r) * DD + d4 * 4];
        if (k0 + r < NN) vb = *(const float4*)&g_xn[(size_t)(k0 + r) * DD + d4 * 4];
        As[(d4 * 4 + 0) * 64 + r] = va.x;
        As[(d4 * 4 + 1) * 64 + r] = va.y;
        As[(d4 * 4 + 2) * 64 + r] = va.z;
        As[(d4 * 4 + 3) * 64 + r] = va.w;
        Bs[(d4 * 4 + 0) * 64 + r] = vb.x;
        Bs[(d4 * 4 + 1) * 64 + r] = vb.y;
        Bs[(d4 * 4 + 2) * 64 + r] = vb.z;
        Bs[(d4 * 4 + 3) * 64 + r] = vb.w;
    }
    __syncthreads();

    int tx = tid & 15;              // key group
    int ty = tid >> 4;              // query group
    float acc[4][4];
    #pragma unroll
    for (int i = 0; i < 4; i++)
        #pragma unroll
        for (int j = 0; j < 4; j++) acc[i][j] = 0.f;

    const float4* A4 = (const float4*)As;
    const float4* B4 = (const float4*)Bs;
    #pragma unroll 8
    for (int d = 0; d < 128; d++) {
        float4 a = A4[d * 16 + ty];
        float4 b = B4[d * 16 + tx];
        acc[0][0] = fmaf(a.x, b.x, acc[0][0]);
        acc[0][1] = fmaf(a.x, b.y, acc[0][1]);
        acc[0][2] = fmaf(a.x, b.z, acc[0][2]);
        acc[0][3] = fmaf(a.x, b.w, acc[0][3]);
        acc[1][0] = fmaf(a.y, b.x, acc[1][0]);
        acc[1][1] = fmaf(a.y, b.y, acc[1][1]);
        acc[1][2] = fmaf(a.y, b.z, acc[1][2]);
        acc[1][3] = fmaf(a.y, b.w, acc[1][3]);
        acc[2][0] = fmaf(a.z, b.x, acc[2][0]);
        acc[2][1] = fmaf(a.z, b.y, acc[2][1]);
        acc[2][2] = fmaf(a.z, b.z, acc[2][2]);
        acc[2][3] = fmaf(a.z, b.w, acc[2][3]);
        acc[3][0] = fmaf(a.w, b.x, acc[3][0]);
        acc[3][1] = fmaf(a.w, b.y, acc[3][1]);
        acc[3][2] = fmaf(a.w, b.z, acc[3][2]);
        acc[3][3] = fmaf(a.w, b.w, acc[3][3]);
    }

    #pragma unroll
    for (int qi = 0; qi < 4; qi++) {
        int q = q0 + ty * 4 + qi;
        if (q >= NN) continue;
        int kk = k0 + tx * 4;
        size_t base = (size_t)q * NN + kk;
        if (kk + 3 < NN) {
            float4 v = make_float4(acc[qi][0], acc[qi][1], acc[qi][2], acc[qi][3]);
            *(float4*)&g_sim[base] = v;
        } else {
            #pragma unroll
            for (int j = 0; j < 4; j++)
                if (kk + j < NN) g_sim[base + j] = acc[qi][j];
        }
    }
}

// ---------------- 3) top-16 per row (JAX semantics: value desc, index asc) ---
__device__ __forceinline__ void insert16(float* mv, int* mi, float v, int ix) {
    if (!(v > mv[15] || (v == mv[15] && ix < mi[15]))) return;
    int p = 15;
    while (p > 0 && (v > mv[p - 1] || (v == mv[p - 1] && ix < mi[p - 1]))) {
        mv[p] = mv[p - 1]; mi[p] = mi[p - 1]; --p;
    }
    mv[p] = v; mi[p] = ix;
}

__global__ void topk_kernel() {
    __shared__ float sval[256 * 16];
    __shared__ int   sidx[256 * 16];
    int row = blockIdx.x;
    int tid = threadIdx.x;
    const float* s = g_sim + (size_t)row * NN;
    float* mv = sval + tid * 16;
    int*   mi = sidx + tid * 16;
    #pragma unroll
    for (int p = 0; p < 16; p++) { mv[p] = -1e30f; mi[p] = 0x7fffffff; }
    float thr = -1e30f; int thri = 0x7fffffff;
    for (int j = tid; j < NN; j += 256) {
        float v = s[j];
        if (v > thr || (v == thr && j < thri)) {
            insert16(mv, mi, v, j);
            thr = mv[15]; thri = mi[15];
        }
    }
    __syncthreads();
    // stage 1: 16 threads each merge 16 lists into list (t*16)
    if (tid < 16) {
        float* dv = sval + (tid * 16) * 16;
        int*   di = sidx + (tid * 16) * 16;
        for (int t = tid * 16 + 1; t < tid * 16 + 16; t++) {
            const float* svp = sval + t * 16;
            const int*   sip = sidx + t * 16;
            for (int p = 0; p < 16; p++) {
                float v = svp[p]; int ix = sip[p];
                if (!(v > dv[15] || (v == dv[15] && ix < di[15]))) break; // sorted source
                insert16(dv, di, v, ix);
            }
        }
    }
    __syncthreads();
    // stage 2: thread 0 merges the 16 stage-1 lists
    if (tid == 0) {
        float* dv = sval;       // list of thread 0
        int*   di = sidx;
        for (int g = 1; g < 16; g++) {
            const float* svp = sval + (g * 16) * 16;
            const int*   sip = sidx + (g * 16) * 16;
            for (int p = 0; p < 16; p++) {
                float v = svp[p]; int ix = sip[p];
                if (!(v > dv[15] || (v == dv[15] && ix < di[15]))) break;
                insert16(dv, di, v, ix);
            }
        }
        for (int p = 0; p < 16; p++) g_knn[(size_t)row * 16 + p] = di[p];
    }
}

// ---------------- 4a) VertexConv k=16: mult + softmax + coef (NB=8) ---------
__global__ void vc16_kernel(const float* __restrict__ feats,
                            const int* __restrict__ ids,
                            const int* __restrict__ table, int tstride, int toff,
                            int knn_mode,
                            const float* __restrict__ wKK,
                            const float* __restrict__ bKK,
                            const float* __restrict__ wK1,
                            int tslot) {
    extern __shared__ float Xs[];               // [8][16][128] = 64KB
    __shared__ float P[256];
    __shared__ float wk1s[16];
    int tid = threadIdx.x;
    int n0 = blockIdx.x * 8;

    for (int e = tid; e < 8 * 16 * 32; e += 256) {
        int d4 = e & 31; int rem = e >> 5;
        int i = rem & 15; int nl = rem >> 4;
        int n = n0 + nl;
        float4 v = make_float4(0.f, 0.f, 0.f, 0.f);
        if (n < NN) {
            int r = ids[n];
            int src = knn_mode ? g_knn[(size_t)r * 16 + i]
                               : table[(size_t)r * tstride + toff + i];
            v = *(const float4*)&feats[(size_t)src * DD + d4 * 4];
        }
        *(float4*)&Xs[((size_t)(nl * 16 + i)) * DD + d4 * 4] = v;
    }
    if (tid < 16) wk1s[tid] = wK1[tid];
    __syncthreads();

    int i = tid >> 4, j = tid & 15;
    const float4* wv = (const float4*)&wKK[(size_t)(i * 16 + j) * DD];
    float acc[8];
    #pragma unroll
    for (int nl = 0; nl < 8; nl++) acc[nl] = 0.f;

    #pragma unroll 4
    for (int d4 = 0; d4 < 32; d4++) {
        float4 w = wv[d4];
        #pragma unroll
        for (int nl = 0; nl < 8; nl++) {
            float4 x = *(const float4*)&Xs[((size_t)(nl * 16 + i)) * DD + d4 * 4];
            acc[nl] = fmaf(w.x, x.x, acc[nl]);
            acc[nl] = fmaf(w.y, x.y, acc[nl]);
            acc[nl] = fmaf(w.z, x.z, acc[nl]);
            acc[nl] = fmaf(w.w, x.w, acc[nl]);
        }
    }

    float b = bKK[tid];   // bKK[i*16+j]
    for (int nl = 0; nl < 8; nl++) {
        float m = acc[nl] + b;
        float mx = m;
        #pragma unroll
        for (int msk = 8; msk >= 1; msk >>= 1)
            mx = fmaxf(mx, __shfl_xor_sync(0xffffffffu, mx, msk));
        float ev = __expf(m - mx);
        float sum = ev;
        #pragma unroll
        for (int msk = 8; msk >= 1; msk >>= 1)
            sum += __shfl_xor_sync(0xffffffffu, sum, msk);
        P[tid] = ev / sum;
        __syncthreads();
        if (tid < 16) {
            float c = 0.f;
            #pragma unroll
            for (int ii = 0; ii < 16; ii++) c = fmaf(wk1s[ii], P[ii * 16 + tid], c);
            int n = n0 + nl;
            if (n < NN) g_coef[((size_t)tslot * NN + n) * 32 + tid] = c;
        }
        __syncthreads();
    }
}

// ---------------- 4b) VertexConv k=32 (structure), NB=4 ----------------------
__global__ void vc32_kernel(const float* __restrict__ feats,
                            const int* __restrict__ ids,
                            const int* __restrict__ table,
                            const float* __restrict__ wKK,
                            const float* __restrict__ bKK,
                            const float* __restrict__ wK1) {
    extern __shared__ float Xs[];               // [4][32][128] = 64KB
    __shared__ float P[32 * 32];
    __shared__ float wk1s[32];
    int tid = threadIdx.x;
    int n0 = blockIdx.x * 4;

    for (int e = tid; e < 4 * 32 * 32; e += 256) {
        int d4 = e & 31; int rem = e >> 5;
        int i = rem & 31; int nl = rem >> 5;
        int n = n0 + nl;
        float4 v = make_float4(0.f, 0.f, 0.f, 0.f);
        if (n < NN) {
            int r = ids[n];
            int src = table[(size_t)r * 32 + i];
            v = *(const float4*)&feats[(size_t)src * DD + d4 * 4];
        }
        *(float4*)&Xs[((size_t)(nl * 32 + i)) * DD + d4 * 4] = v;
    }
    if (tid < 32) wk1s[tid] = wK1[tid];
    __syncthreads();

    int j = tid & 31;
    int i0 = tid >> 5;      // 0..7 ; i = i0 + p*8
    float acc[4][4];        // [p][nl]
    #pragma unroll
    for (int p = 0; p < 4; p++)
        #pragma unroll
        for (int nl = 0; nl < 4; nl++) acc[p][nl] = 0.f;

    #pragma unroll 2
    for (int d4 = 0; d4 < 32; d4++) {
        #pragma unroll
        for (int p = 0; p < 4; p++) {
            int i = i0 + p * 8;
            float4 w = ((const float4*)&wKK[(size_t)(i * 32 + j) * DD])[d4];
            #pragma unroll
            for (int nl = 0; nl < 4; nl++) {
                float4 x = *(const float4*)&Xs[((size_t)(nl * 32 + i)) * DD + d4 * 4];
                acc[p][nl] = fmaf(w.x, x.x, acc[p][nl]);
                acc[p][nl] = fmaf(w.y, x.y, acc[p][nl]);
                acc[p][nl] = fmaf(w.z, x.z, acc[p][nl]);
                acc[p][nl] = fmaf(w.w, x.w, acc[p][nl]);
            }
        }
    }

    for (int nl = 0; nl < 4; nl++) {
        #pragma unroll
        for (int p = 0; p < 4; p++) {
            int i = i0 + p * 8;
            float m = acc[p][nl] + bKK[i * 32 + j];
            float mx = m;
            #pragma unroll
            for (int msk = 16; msk >= 1; msk >>= 1)
                mx = fmaxf(mx, __shfl_xor_sync(0xffffffffu, mx, msk));
            float ev = __expf(m - mx);
            float sum = ev;
            #pragma unroll
            for (int msk = 16; msk >= 1; msk >>= 1)
                sum += __shfl_xor_sync(0xffffffffu, sum, msk);
            P[i * 32 + j] = ev / sum;
        }
        __syncthreads();
        if (tid < 32) {
            float c = 0.f;
            #pragma unroll
            for (int ii = 0; ii < 32; ii++) c = fmaf(wk1s[ii], P[ii * 32 + tid], c);
            int n = n0 + nl;
            if (n < NN) g_coef[((size_t)4 * NN + n) * 32 + tid] = c;
        }
        __syncthreads();
    }
}

// ---------------- 5) final: gather + edge attention + fc + relu --------------
__global__ void final_kernel(const float* __restrict__ feats,
                             const int* __restrict__ ids,
                             const int* __restrict__ cluster_idx,
                             const int* __restrict__ struct_idx,
                             const float* __restrict__ bK1_c,
                             const float* __restrict__ bK1_n,
                             const float* __restrict__ bK1_s,
                             const float* __restrict__ ec_w1,
                             const float* __restrict__ ec_b1,
                             const float* __restrict__ ec_w2,
                             const float* __restrict__ ec_b2,
                             const float* __restrict__ fc_w,
                             const float* __restrict__ fc_b,
                             float* __restrict__ out) {
    __shared__ float HE[5][128];
    __shared__ float cj[32];
    __shared__ float hsh[160];
    __shared__ float sc[8];
    __shared__ float aggs[128];
    int n = blockIdx.x;
    int tid = threadIdx.x;      // 128 threads = d
    int row = ids[n];

    for (int t = 0; t < 5; t++) {
        int k = (t == 4) ? 32 : 16;
        if (tid < k) cj[tid] = g_coef[((size_t)t * NN + n) * 32 + tid];
        __syncthreads();
        float he;
        if (t < 3)       he = bK1_c[0];
        else if (t == 3) he = bK1_n[0];
        else             he = bK1_s[0];
        for (int j = 0; j < k; j++) {
            int src;
            if (t < 3)       src = cluster_idx[(size_t)row * 48 + t * 16 + j];
            else if (t == 3) src = g_knn[(size_t)row * 16 + j];
            else             src = struct_idx[(size_t)row * 32 + j];
            he = fmaf(cj[j], feats[(size_t)src * DD + tid], he);
        }
        HE[t][tid] = he;
        __syncthreads();
    }

    // attention MLP: h[t][hid] = relu(HE[t]·w1[:,hid] + b1[hid])
    for (int e = tid; e < 160; e += 128) {
        int t = e >> 5, h = e & 31;
        float s = ec_b1[h];
        for (int d = 0; d < 128; d++) s = fmaf(HE[t][d], ec_w1[d * 32 + h], s);
        hsh[e] = fmaxf(s, 0.f);
    }
    __syncthreads();
    if (tid < 5) {
        float s = ec_b2[0];
        #pragma unroll
        for (int h = 0; h < 32; h++) s = fmaf(hsh[tid * 32 + h], ec_w2[h], s);
        sc[tid] = s;
    }
    __syncthreads();
    if (tid == 0) {
        float mx = sc[0];
        for (int t = 1; t < 5; t++) mx = fmaxf(mx, sc[t]);
        float sm = 0.f;
        for (int t = 0; t < 5; t++) { float e = __expf(sc[t] - mx); sc[t] = e; sm += e; }
        for (int t = 0; t < 5; t++) sc[t] /= sm;
    }
    __syncthreads();
    float a = 0.f;
    #pragma unroll
    for (int t = 0; t < 5; t++) a = fmaf(sc[t], HE[t][tid], a);
    aggs[tid] = a;
    __syncthreads();
    float o = fc_b[tid];
    for (int d = 0; d < 128; d++) o = fmaf(aggs[d], fc_w[d * 128 + tid], o);
    out[(size_t)n * 128 + tid] = fmaxf(o, 0.f);
}

// ---------------- launch -----------------------------------------------------
extern "C" void kernel_launch(void* const* d_in, const int* in_sizes, int n_in,
                              void* d_out, int out_size) {
    const int*   ids         = (const int*)d_in[0];
    const float* feats       = (const float*)d_in[1];
    const int*   cluster_idx = (const int*)d_in[2];
    const int*   struct_idx  = (const int*)d_in[3];
    // d_in[4] = epo (static: all branches active)
    const float* wKK_c = (const float*)d_in[5];
    const float* bKK_c = (const float*)d_in[6];
    const float* wK1_c = (const float*)d_in[7];
    const float* bK1_c = (const float*)d_in[8];
    const float* wKK_n = (const float*)d_in[9];
    const float* bKK_n = (const float*)d_in[10];
    const float* wK1_n = (const float*)d_in[11];
    const float* bK1_n = (const float*)d_in[12];
    const float* wKK_s = (const float*)d_in[13];
    const float* bKK_s = (const float*)d_in[14];
    const float* wK1_s = (const float*)d_in[15];
    const float* bK1_s = (const float*)d_in[16];
    const float* ec_w1 = (const float*)d_in[17];
    const float* ec_b1 = (const float*)d_in[18];
    const float* ec_w2 = (const float*)d_in[19];
    const float* ec_b2 = (const float*)d_in[20];
    const float* fc_w  = (const float*)d_in[21];
    const float* fc_b  = (const float*)d_in[22];
    float* out = (float*)d_out;

    cudaFuncSetAttribute(sim_gemm,    cudaFuncAttributeMaxDynamicSharedMemorySize, 65536);
    cudaFuncSetAttribute(vc16_kernel, cudaFuncAttributeMaxDynamicSharedMemorySize, 65536);
    cudaFuncSetAttribute(vc32_kernel, cudaFuncAttributeMaxDynamicSharedMemorySize, 65536);

    norm_kernel<<<NN, 128>>>(feats);

    dim3 gg((NN + 63) / 64, (NN + 63) / 64);
    sim_gemm<<<gg, 256, 65536>>>();

    topk_kernel<<<NN, 256>>>();

    // cluster branches (share wKK_c), knn branch, struct branch
    vc16_kernel<<<(NN + 7) / 8, 256, 65536>>>(feats, ids, cluster_idx, 48, 0,  0, wKK_c, bKK_c, wK1_c, 0);
    vc16_kernel<<<(NN + 7) / 8, 256, 65536>>>(feats, ids, cluster_idx, 48, 16, 0, wKK_c, bKK_c, wK1_c, 1);
    vc16_kernel<<<(NN + 7) / 8, 256, 65536>>>(feats, ids, cluster_idx, 48, 32, 0, wKK_c, bKK_c, wK1_c, 2);
    vc16_kernel<<<(NN + 7) / 8, 256, 65536>>>(feats, ids, cluster_idx, 0,  0,  1, wKK_n, bKK_n, wK1_n, 3);
    vc32_kernel<<<(NN + 3) / 4, 256, 65536>>>(feats, ids, struct_idx, wKK_s, bKK_s, wK1_s);

    final_kernel<<<NN, 128>>>(feats, ids, cluster_idx, struct_idx,
                              bK1_c, bK1_n, bK1_s,
                              ec_w1, ec_b1, ec_w2, ec_b2, fc_w, fc_b, out);
}

// round 3
// speedup vs baseline: 3.4593x; 3.4593x over previous
#include <cuda_runtime.h>
#include <cstdint>
#include <cstddef>

#define NN 10000
#define DD 128
#define KSPLIT 4
#define NQT 157          // ceil(10000/64)

// ---------------- scratch (device globals; no allocations allowed) ----------
__device__ float g_xn[(size_t)NN * DD];                       // normalized feats
__device__ unsigned long long g_part[(size_t)NN * KSPLIT * 16]; // partial topk keys
__device__ int   g_knn[(size_t)NN * 16];                      // top-16 per row
__device__ float g_coef[(size_t)5 * NN * 32];                 // per-branch coef[j]

// ---------------- 1) normalize ----------------------------------------------
__global__ void norm_kernel(const float* __restrict__ feats) {
    int n = blockIdx.x;
    int tid = threadIdx.x;                          // 128 threads = d
    float v = feats[(size_t)n * DD + tid];
    float s = v * v;
    #pragma unroll
    for (int m = 16; m >= 1; m >>= 1) s += __shfl_xor_sync(0xffffffffu, s, m);
    __shared__ float ws[4];
    if ((tid & 31) == 0) ws[tid >> 5] = s;
    __syncthreads();
    float tot = ws[0] + ws[1] + ws[2] + ws[3];
    float nrm = fmaxf(sqrtf(tot), 1e-12f);
    g_xn[(size_t)n * DD + tid] = v / nrm;
}

// ---------------- packed topk key helpers ------------------------------------
// key = (monotone-mapped fp32 value)<<32 | ~j  : larger key = (bigger value, or
// equal value with smaller index). Matches JAX stable top_k tie-break.
__device__ __forceinline__ void tk_insert(unsigned long long (&tk)[16],
                                          float v, int j) {
    unsigned u = __float_as_uint(v);
    u = (u & 0x80000000u) ? ~u : (u | 0x80000000u);
    unsigned long long key = ((unsigned long long)u << 32) | (unsigned)(~j);
    if (key > tk[15]) {
        #pragma unroll
        for (int p = 0; p < 16; p++) {
            unsigned long long cur = tk[p];
            bool gt = cur > key;
            tk[p] = gt ? cur : key;
            key   = gt ? key : cur;
        }
    }
}

__device__ __forceinline__ void tk_insert_key(unsigned long long (&tk)[16],
                                              unsigned long long key) {
    if (key > tk[15]) {
        #pragma unroll
        for (int p = 0; p < 16; p++) {
            unsigned long long cur = tk[p];
            bool gt = cur > key;
            tk[p] = gt ? cur : key;
            key   = gt ? key : cur;
        }
    }
}

// ---------------- 2) fused sim GEMM + top-16 (no 400MB materialization) ------
// Block: 64 query rows, loops over every KSPLIT-th 64-key tile.
// smem: As [128][64] (persistent) | Bs [128][64] | Cs [64][68]
__global__ __launch_bounds__(256, 2) void simtopk_kernel() {
    extern __shared__ char smem_raw[];
    float* As = (float*)smem_raw;                        // 32KB
    float* Bs = (float*)(smem_raw + 32768);              // 32KB
    float* Cs = (float*)(smem_raw + 65536);              // 64*68*4 = 17408B
    unsigned long long* Mk = (unsigned long long*)(smem_raw + 32768); // alias Bs

    int tid = threadIdx.x;
    int q0 = blockIdx.x * 64;
    int ks = blockIdx.y;

    // load A tile once (transposed [d][row])
    for (int e = tid; e < 2048; e += 256) {
        int d4 = e >> 6;
        int r  = e & 63;
        float4 va = make_float4(0.f, 0.f, 0.f, 0.f);
        if (q0 + r < NN) va = *(const float4*)&g_xn[(size_t)(q0 + r) * DD + d4 * 4];
        As[(d4 * 4 + 0) * 64 + r] = va.x;
        As[(d4 * 4 + 1) * 64 + r] = va.y;
        As[(d4 * 4 + 2) * 64 + r] = va.z;
        As[(d4 * 4 + 3) * 64 + r] = va.w;
    }

    unsigned long long tk[16];
    #pragma unroll
    for (int p = 0; p < 16; p++) tk[p] = 0ull;

    int tx = tid & 15;              // key group (compute phase)
    int ty = tid >> 4;              // query group
    int trow = tid >> 2;            // row (topk phase)
    int tkq  = tid & 3;             // key quarter

    const float4* A4 = (const float4*)As;
    const float4* B4 = (const float4*)Bs;

    for (int kt = ks; kt < NQT; kt += KSPLIT) {
        int k0 = kt * 64;
        __syncthreads();            // prior compute done reading Bs
        for (int e = tid; e < 2048; e += 256) {
            int d4 = e >> 6;
            int r  = e & 63;
            float4 vb = make_float4(0.f, 0.f, 0.f, 0.f);
            if (k0 + r < NN) vb = *(const float4*)&g_xn[(size_t)(k0 + r) * DD + d4 * 4];
            Bs[(d4 * 4 + 0) * 64 + r] = vb.x;
            Bs[(d4 * 4 + 1) * 64 + r] = vb.y;
            Bs[(d4 * 4 + 2) * 64 + r] = vb.z;
            Bs[(d4 * 4 + 3) * 64 + r] = vb.w;
        }
        __syncthreads();

        float acc[4][4];
        #pragma unroll
        for (int i = 0; i < 4; i++)
            #pragma unroll
            for (int j = 0; j < 4; j++) acc[i][j] = 0.f;

        #pragma unroll 8
        for (int d = 0; d < 128; d++) {
            float4 a = A4[d * 16 + ty];
            float4 b = B4[d * 16 + tx];
            acc[0][0] = fmaf(a.x, b.x, acc[0][0]);
            acc[0][1] = fmaf(a.x, b.y, acc[0][1]);
            acc[0][2] = fmaf(a.x, b.z, acc[0][2]);
            acc[0][3] = fmaf(a.x, b.w, acc[0][3]);
            acc[1][0] = fmaf(a.y, b.x, acc[1][0]);
            acc[1][1] = fmaf(a.y, b.y, acc[1][1]);
            acc[1][2] = fmaf(a.y, b.z, acc[1][2]);
            acc[1][3] = fmaf(a.y, b.w, acc[1][3]);
            acc[2][0] = fmaf(a.z, b.x, acc[2][0]);
            acc[2][1] = fmaf(a.z, b.y, acc[2][1]);
            acc[2][2] = fmaf(a.z, b.z, acc[2][2]);
            acc[2][3] = fmaf(a.z, b.w, acc[2][3]);
            acc[3][0] = fmaf(a.w, b.x, acc[3][0]);
            acc[3][1] = fmaf(a.w, b.y, acc[3][1]);
            acc[3][2] = fmaf(a.w, b.z, acc[3][2]);
            acc[3][3] = fmaf(a.w, b.w, acc[3][3]);
        }

        #pragma unroll
        for (int qi = 0; qi < 4; qi++)
            *(float4*)&Cs[(ty * 4 + qi) * 68 + tx * 4] =
                make_float4(acc[qi][0], acc[qi][1], acc[qi][2], acc[qi][3]);
        __syncthreads();

        // topk update: thread handles row trow, keys [k0 + tkq*16, +16)
        const float4* c4 = (const float4*)&Cs[trow * 68 + tkq * 16];
        #pragma unroll
        for (int g = 0; g < 4; g++) {
            float4 v = c4[g];
            int jb = k0 + tkq * 16 + g * 4;
            if (jb + 3 < NN) {
                tk_insert(tk, v.x, jb + 0);
                tk_insert(tk, v.y, jb + 1);
                tk_insert(tk, v.z, jb + 2);
                tk_insert(tk, v.w, jb + 3);
            } else {
                if (jb + 0 < NN) tk_insert(tk, v.x, jb + 0);
                if (jb + 1 < NN) tk_insert(tk, v.y, jb + 1);
                if (jb + 2 < NN) tk_insert(tk, v.z, jb + 2);
                if (jb + 3 < NN) tk_insert(tk, v.w, jb + 3);
            }
        }
    }
    __syncthreads();                // done with Bs/Cs; alias Bs as Mk

    #pragma unroll
    for (int p = 0; p < 16; p++) Mk[trow * 64 + tkq * 16 + p] = tk[p];
    __syncthreads();

    if (tid < 64) {
        int q = q0 + tid;
        const unsigned long long* src = &Mk[tid * 64];
        unsigned long long r[16];
        #pragma unroll
        for (int p = 0; p < 16; p++) r[p] = src[p];     // kq=0 list (sorted)
        for (int e = 16; e < 64; e++) tk_insert_key(r, src[e]);
        if (q < NN) {
            #pragma unroll
            for (int p = 0; p < 16; p++)
                g_part[((size_t)q * KSPLIT + ks) * 16 + p] = r[p];
        }
    }
}

// ---------------- 3) merge the KSPLIT partial lists per row ------------------
__global__ void knn_merge_kernel() {
    int row = blockIdx.x * 128 + threadIdx.x;
    if (row >= NN) return;
    const unsigned long long* src = &g_part[(size_t)row * (KSPLIT * 16)];
    unsigned long long r[16];
    #pragma unroll
    for (int p = 0; p < 16; p++) r[p] = src[p];
    for (int e = 16; e < KSPLIT * 16; e++) tk_insert_key(r, src[e]);
    #pragma unroll
    for (int p = 0; p < 16; p++)
        g_knn[(size_t)row * 16 + p] = (int)(~(unsigned)(r[p] & 0xffffffffu));
}

// ---------------- 4a) VertexConv k=16 x 4 branches in one launch -------------
__global__ void vc16_all_kernel(const float* __restrict__ feats,
                                const int* __restrict__ ids,
                                const int* __restrict__ cluster_idx,
                                const float* __restrict__ wKK_c,
                                const float* __restrict__ bKK_c,
                                const float* __restrict__ wK1_c,
                                const float* __restrict__ wKK_n,
                                const float* __restrict__ bKK_n,
                                const float* __restrict__ wK1_n) {
    extern __shared__ float Xs[];               // [8][16][128] = 64KB
    __shared__ float P[256];
    __shared__ float wk1s[16];
    int tid = threadIdx.x;
    int n0 = blockIdx.x * 8;
    int br = blockIdx.y;                        // 0,1,2 = cluster; 3 = knn
    const float* wKK = (br < 3) ? wKK_c : wKK_n;
    const float* bKK = (br < 3) ? bKK_c : bKK_n;
    const float* wK1 = (br < 3) ? wK1_c : wK1_n;

    for (int e = tid; e < 8 * 16 * 32; e += 256) {
        int d4 = e & 31; int rem = e >> 5;
        int i = rem & 15; int nl = rem >> 4;
        int n = n0 + nl;
        float4 v = make_float4(0.f, 0.f, 0.f, 0.f);
        if (n < NN) {
            int r = ids[n];
            int src = (br < 3) ? cluster_idx[(size_t)r * 48 + br * 16 + i]
                               : g_knn[(size_t)r * 16 + i];
            v = *(const float4*)&feats[(size_t)src * DD + d4 * 4];
        }
        *(float4*)&Xs[((size_t)(nl * 16 + i)) * DD + d4 * 4] = v;
    }
    if (tid < 16) wk1s[tid] = wK1[tid];
    __syncthreads();

    int i = tid >> 4, j = tid & 15;
    const float4* wv = (const float4*)&wKK[(size_t)(i * 16 + j) * DD];
    float acc[8];
    #pragma unroll
    for (int nl = 0; nl < 8; nl++) acc[nl] = 0.f;

    #pragma unroll 4
    for (int d4 = 0; d4 < 32; d4++) {
        float4 w = wv[d4];
        #pragma unroll
        for (int nl = 0; nl < 8; nl++) {
            float4 x = *(const float4*)&Xs[((size_t)(nl * 16 + i)) * DD + d4 * 4];
            acc[nl] = fmaf(w.x, x.x, acc[nl]);
            acc[nl] = fmaf(w.y, x.y, acc[nl]);
            acc[nl] = fmaf(w.z, x.z, acc[nl]);
            acc[nl] = fmaf(w.w, x.w, acc[nl]);
        }
    }

    float b = bKK[tid];   // bKK[i*16+j]
    for (int nl = 0; nl < 8; nl++) {
        float m = acc[nl] + b;
        float mx = m;
        #pragma unroll
        for (int msk = 8; msk >= 1; msk >>= 1)
            mx = fmaxf(mx, __shfl_xor_sync(0xffffffffu, mx, msk));
        float ev = __expf(m - mx);
        float sum = ev;
        #pragma unroll
        for (int msk = 8; msk >= 1; msk >>= 1)
            sum += __shfl_xor_sync(0xffffffffu, sum, msk);
        P[tid] = ev / sum;
        __syncthreads();
        if (tid < 16) {
            float c = 0.f;
            #pragma unroll
            for (int ii = 0; ii < 16; ii++) c = fmaf(wk1s[ii], P[ii * 16 + tid], c);
            int n = n0 + nl;
            if (n < NN) g_coef[((size_t)br * NN + n) * 32 + tid] = c;
        }
        __syncthreads();
    }
}

// ---------------- 4b) VertexConv k=32 (structure), NB=4 ----------------------
__global__ void vc32_kernel(const float* __restrict__ feats,
                            const int* __restrict__ ids,
                            const int* __restrict__ table,
                            const float* __restrict__ wKK,
                            const float* __restrict__ bKK,
                            const float* __restrict__ wK1) {
    extern __shared__ float Xs[];               // [4][32][128] = 64KB
    __shared__ float P[32 * 32];
    __shared__ float wk1s[32];
    int tid = threadIdx.x;
    int n0 = blockIdx.x * 4;

    for (int e = tid; e < 4 * 32 * 32; e += 256) {
        int d4 = e & 31; int rem = e >> 5;
        int i = rem & 31; int nl = rem >> 5;
        int n = n0 + nl;
        float4 v = make_float4(0.f, 0.f, 0.f, 0.f);
        if (n < NN) {
            int r = ids[n];
            int src = table[(size_t)r * 32 + i];
            v = *(const float4*)&feats[(size_t)src * DD + d4 * 4];
        }
        *(float4*)&Xs[((size_t)(nl * 32 + i)) * DD + d4 * 4] = v;
    }
    if (tid < 32) wk1s[tid] = wK1[tid];
    __syncthreads();

    int j = tid & 31;
    int i0 = tid >> 5;      // 0..7 ; i = i0 + p*8
    float acc[4][4];        // [p][nl]
    #pragma unroll
    for (int p = 0; p < 4; p++)
        #pragma unroll
        for (int nl = 0; nl < 4; nl++) acc[p][nl] = 0.f;

    #pragma unroll 2
    for (int d4 = 0; d4 < 32; d4++) {
        #pragma unroll
        for (int p = 0; p < 4; p++) {
            int i = i0 + p * 8;
            float4 w = ((const float4*)&wKK[(size_t)(i * 32 + j) * DD])[d4];
            #pragma unroll
            for (int nl = 0; nl < 4; nl++) {
                float4 x = *(const float4*)&Xs[((size_t)(nl * 32 + i)) * DD + d4 * 4];
                acc[p][nl] = fmaf(w.x, x.x, acc[p][nl]);
                acc[p][nl] = fmaf(w.y, x.y, acc[p][nl]);
                acc[p][nl] = fmaf(w.z, x.z, acc[p][nl]);
                acc[p][nl] = fmaf(w.w, x.w, acc[p][nl]);
            }
        }
    }

    for (int nl = 0; nl < 4; nl++) {
        #pragma unroll
        for (int p = 0; p < 4; p++) {
            int i = i0 + p * 8;
            float m = acc[p][nl] + bKK[i * 32 + j];
            float mx = m;
            #pragma unroll
            for (int msk = 16; msk >= 1; msk >>= 1)
                mx = fmaxf(mx, __shfl_xor_sync(0xffffffffu, mx, msk));
            float ev = __expf(m - mx);
            float sum = ev;
            #pragma unroll
            for (int msk = 16; msk >= 1; msk >>= 1)
                sum += __shfl_xor_sync(0xffffffffu, sum, msk);
            P[i * 32 + j] = ev / sum;
        }
        __syncthreads();
        if (tid < 32) {
            float c = 0.f;
            #pragma unroll
            for (int ii = 0; ii < 32; ii++) c = fmaf(wk1s[ii], P[ii * 32 + tid], c);
            int n = n0 + nl;
            if (n < NN) g_coef[((size_t)4 * NN + n) * 32 + tid] = c;
        }
        __syncthreads();
    }
}

// ---------------- 5) final: gather + edge attention + fc + relu --------------
__global__ void final_kernel(const float* __restrict__ feats,
                             const int* __restrict__ ids,
                             const int* __restrict__ cluster_idx,
                             const int* __restrict__ struct_idx,
                             const float* __restrict__ bK1_c,
                             const float* __restrict__ bK1_n,
                             const float* __restrict__ bK1_s,
                             const float* __restrict__ ec_w1,
                             const float* __restrict__ ec_b1,
                             const float* __restrict__ ec_w2,
                             const float* __restrict__ ec_b2,
                             const float* __restrict__ fc_w,
                             const float* __restrict__ fc_b,
                             float* __restrict__ out) {
    __shared__ float HE[5][128];
    __shared__ float cj[32];
    __shared__ float hsh[160];
    __shared__ float sc[8];
    __shared__ float aggs[128];
    int n = blockIdx.x;
    int tid = threadIdx.x;      // 128 threads = d
    int row = ids[n];

    for (int t = 0; t < 5; t++) {
        int k = (t == 4) ? 32 : 16;
        if (tid < k) cj[tid] = g_coef[((size_t)t * NN + n) * 32 + tid];
        __syncthreads();
        float he;
        if (t < 3)       he = bK1_c[0];
        else if (t == 3) he = bK1_n[0];
        else             he = bK1_s[0];
        for (int j = 0; j < k; j++) {
            int src;
            if (t < 3)       src = cluster_idx[(size_t)row * 48 + t * 16 + j];
            else if (t == 3) src = g_knn[(size_t)row * 16 + j];
            else             src = struct_idx[(size_t)row * 32 + j];
            he = fmaf(cj[j], feats[(size_t)src * DD + tid], he);
        }
        HE[t][tid] = he;
        __syncthreads();
    }

    for (int e = tid; e < 160; e += 128) {
        int t = e >> 5, h = e & 31;
        float s = ec_b1[h];
        for (int d = 0; d < 128; d++) s = fmaf(HE[t][d], ec_w1[d * 32 + h], s);
        hsh[e] = fmaxf(s, 0.f);
    }
    __syncthreads();
    if (tid < 5) {
        float s = ec_b2[0];
        #pragma unroll
        for (int h = 0; h < 32; h++) s = fmaf(hsh[tid * 32 + h], ec_w2[h], s);
        sc[tid] = s;
    }
    __syncthreads();
    if (tid == 0) {
        float mx = sc[0];
        for (int t = 1; t < 5; t++) mx = fmaxf(mx, sc[t]);
        float sm = 0.f;
        for (int t = 0; t < 5; t++) { float e = __expf(sc[t] - mx); sc[t] = e; sm += e; }
        for (int t = 0; t < 5; t++) sc[t] /= sm;
    }
    __syncthreads();
    float a = 0.f;
    #pragma unroll
    for (int t = 0; t < 5; t++) a = fmaf(sc[t], HE[t][tid], a);
    aggs[tid] = a;
    __syncthreads();
    float o = fc_b[tid];
    for (int d = 0; d < 128; d++) o = fmaf(aggs[d], fc_w[d * 128 + tid], o);
    out[(size_t)n * 128 + tid] = fmaxf(o, 0.f);
}

// ---------------- launch -----------------------------------------------------
extern "C" void kernel_launch(void* const* d_in, const int* in_sizes, int n_in,
                              void* d_out, int out_size) {
    const int*   ids         = (const int*)d_in[0];
    const float* feats       = (const float*)d_in[1];
    const int*   cluster_idx = (const int*)d_in[2];
    const int*   struct_idx  = (const int*)d_in[3];
    // d_in[4] = epo (static: all branches active)
    const float* wKK_c = (const float*)d_in[5];
    const float* bKK_c = (const float*)d_in[6];
    const float* wK1_c = (const float*)d_in[7];
    const float* bK1_c = (const float*)d_in[8];
    const float* wKK_n = (const float*)d_in[9];
    const float* bKK_n = (const float*)d_in[10];
    const float* wK1_n = (const float*)d_in[11];
    const float* bK1_n = (const float*)d_in[12];
    const float* wKK_s = (const float*)d_in[13];
    const float* bKK_s = (const float*)d_in[14];
    const float* wK1_s = (const float*)d_in[15];
    const float* bK1_s = (const float*)d_in[16];
    const float* ec_w1 = (const float*)d_in[17];
    const float* ec_b1 = (const float*)d_in[18];
    const float* ec_w2 = (const float*)d_in[19];
    const float* ec_b2 = (const float*)d_in[20];
    const float* fc_w  = (const float*)d_in[21];
    const float* fc_b  = (const float*)d_in[22];
    float* out = (float*)d_out;

    cudaFuncSetAttribute(simtopk_kernel,  cudaFuncAttributeMaxDynamicSharedMemorySize, 82944);
    cudaFuncSetAttribute(vc16_all_kernel, cudaFuncAttributeMaxDynamicSharedMemorySize, 65536);
    cudaFuncSetAttribute(vc32_kernel,     cudaFuncAttributeMaxDynamicSharedMemorySize, 65536);

    norm_kernel<<<NN, 128>>>(feats);

    dim3 gg(NQT, KSPLIT);
    simtopk_kernel<<<gg, 256, 82944>>>();
    knn_merge_kernel<<<(NN + 127) / 128, 128>>>();

    dim3 gv((NN + 7) / 8, 4);
    vc16_all_kernel<<<gv, 256, 65536>>>(feats, ids, cluster_idx,
                                        wKK_c, bKK_c, wK1_c,
                                        wKK_n, bKK_n, wK1_n);
    vc32_kernel<<<(NN + 3) / 4, 256, 65536>>>(feats, ids, struct_idx, wKK_s, bKK_s, wK1_s);

    final_kernel<<<NN, 128>>>(feats, ids, cluster_idx, struct_idx,
                              bK1_c, bK1_n, bK1_s,
                              ec_w1, ec_b1, ec_w2, ec_b2, fc_w, fc_b, out);
}